// round 5
// baseline (speedup 1.0000x reference)
#include <cuda_runtime.h>
#include <cstdint>

// out = x * (1 - mask), mask broadcasts over C=3.
// x:    [B=64, C=3, H=512, W=512] f32   -- streamed, zero reuse  -> __ldcs
// out:  same shape                      -- streamed, never read  -> __stcs
// mask: [B=64, 1,   H=512, W=512] f32   -- 67 MB, reused across graph
//                                          replays via L2 -> default policy
//
// Cache hints keep the mask resident in the 126 MB L2 while the 2x201 MB
// x/out streams are marked evict-first, eliminating the residual ~15 MB of
// mask DRAM misses per launch.

static constexpr int Cc = 3;
static constexpr int HW = 512 * 512;
static constexpr int HW4 = HW / 4;       // 65536 float4 per plane
static constexpr int THREADS = 256;

__global__ __launch_bounds__(THREADS, 8)
void random_mask_kernel(const float4* __restrict__ x,
                        const float4* __restrict__ mask,
                        float4* __restrict__ out) {
    const int b = blockIdx.y;                               // batch
    const int v = blockIdx.x * THREADS + threadIdx.x;       // 0..HW4-1

    const long long mi = (long long)b * HW4 + v;
    const long long x0 = (long long)(b * Cc) * HW4 + v;

    // Issue all loads up front for maximum MLP.
    const float4 mv  = mask[mi];            // normal policy: keep in L2
    const float4 xv0 = __ldcs(&x[x0]);      // streaming: evict-first
    const float4 xv1 = __ldcs(&x[x0 + HW4]);
    const float4 xv2 = __ldcs(&x[x0 + 2 * HW4]);

    float4 w;
    w.x = 1.0f - mv.x;
    w.y = 1.0f - mv.y;
    w.z = 1.0f - mv.z;
    w.w = 1.0f - mv.w;

    float4 o0, o1, o2;
    o0.x = xv0.x * w.x; o0.y = xv0.y * w.y; o0.z = xv0.z * w.z; o0.w = xv0.w * w.w;
    o1.x = xv1.x * w.x; o1.y = xv1.y * w.y; o1.z = xv1.z * w.z; o1.w = xv1.w * w.w;
    o2.x = xv2.x * w.x; o2.y = xv2.y * w.y; o2.z = xv2.z * w.z; o2.w = xv2.w * w.w;

    __stcs(&out[x0],           o0);         // streaming store
    __stcs(&out[x0 + HW4],     o1);
    __stcs(&out[x0 + 2 * HW4], o2);
}

extern "C" void kernel_launch(void* const* d_in, const int* in_sizes, int n_in,
                              void* d_out, int out_size) {
    const float4* x    = (const float4*)d_in[0];
    const float4* mask = (const float4*)d_in[1];
    float4* out        = (float4*)d_out;

    const int B = in_sizes[1] / HW;          // 64
    dim3 grid(HW4 / THREADS, B);             // (256, 64)
    random_mask_kernel<<<grid, THREADS>>>(x, mask, out);
}

// round 6
// speedup vs baseline: 1.2201x; 1.2201x over previous
#include <cuda_runtime.h>
#include <cstdint>

// out = x * (1 - mask), mask broadcasts over C=3.
// x:    [B=64, C=3, H=512, W=512] f32
// mask: [B=64, 1,   H=512, W=512] f32, values exactly 0.0 or 1.0 in large
//       coherent rectangles (courtain/center/border; 'patches' is a no-op).
//
// Key trick: where mask==1 the output is exactly 0.0f, so the three x-plane
// loads are skipped entirely (~35% of x traffic). Mask rectangles are huge,
// so the branch is warp-uniform almost everywhere and predicated-off LDGs
// never fetch their sectors.

static constexpr int Cc = 3;
static constexpr int HW = 512 * 512;
static constexpr int HW4 = HW / 4;       // 65536 float4 per plane
static constexpr int THREADS = 256;

__global__ __launch_bounds__(THREADS, 8)
void random_mask_kernel(const float4* __restrict__ x,
                        const float4* __restrict__ mask,
                        float4* __restrict__ out) {
    const int b = blockIdx.y;                               // batch
    const int v = blockIdx.x * THREADS + threadIdx.x;       // 0..HW4-1

    const long long mi = (long long)b * HW4 + v;
    const long long x0 = (long long)(b * Cc) * HW4 + v;

    const float4 mv = mask[mi];

    const bool fully_masked = (mv.x == 1.0f) & (mv.y == 1.0f) &
                              (mv.z == 1.0f) & (mv.w == 1.0f);

    if (fully_masked) {
        // out = 0 exactly; no need to touch x.
        const float4 z = make_float4(0.0f, 0.0f, 0.0f, 0.0f);
        out[x0]           = z;
        out[x0 + HW4]     = z;
        out[x0 + 2 * HW4] = z;
        return;
    }

    // Issue all loads up front for maximum MLP.
    const float4 xv0 = x[x0];
    const float4 xv1 = x[x0 + HW4];
    const float4 xv2 = x[x0 + 2 * HW4];

    float4 w;
    w.x = 1.0f - mv.x;
    w.y = 1.0f - mv.y;
    w.z = 1.0f - mv.z;
    w.w = 1.0f - mv.w;

    float4 o0, o1, o2;
    o0.x = xv0.x * w.x; o0.y = xv0.y * w.y; o0.z = xv0.z * w.z; o0.w = xv0.w * w.w;
    o1.x = xv1.x * w.x; o1.y = xv1.y * w.y; o1.z = xv1.z * w.z; o1.w = xv1.w * w.w;
    o2.x = xv2.x * w.x; o2.y = xv2.y * w.y; o2.z = xv2.z * w.z; o2.w = xv2.w * w.w;

    out[x0]           = o0;
    out[x0 + HW4]     = o1;
    out[x0 + 2 * HW4] = o2;
}

extern "C" void kernel_launch(void* const* d_in, const int* in_sizes, int n_in,
                              void* d_out, int out_size) {
    const float4* x    = (const float4*)d_in[0];
    const float4* mask = (const float4*)d_in[1];
    float4* out        = (float4*)d_out;

    const int B = in_sizes[1] / HW;          // 64
    dim3 grid(HW4 / THREADS, B);             // (256, 64)
    random_mask_kernel<<<grid, THREADS>>>(x, mask, out);
}